// round 13
// baseline (speedup 1.0000x reference)
#include <cuda_runtime.h>
#include <cuda_fp16.h>
#include <cstdint>

#define Bb 4
#define Ss 2048
#define DM 1024
#define Hh 16
#define Dh 64
// base-2 domain constants
#define SCALE2 0.18033688011112042f   /* 0.125 * log2(e) */
#define BIG2   1.4426950408889634e10f /* 1e10 * log2(e) */

#define XN 8388608ULL   /* Bb*Ss*DM */
#define WN 1048576ULL   /* DM*DM */

// Scratch (allocation-free rule: __device__ globals).
__device__ __half g_qh[Bb * Hh * Ss * Dh];
__device__ __half g_kh[Bb * Hh * Ss * Dh];
__device__ __half g_vh[Bb * Hh * Ss * Dh];
__device__ __half g_xh[3 * XN];   // fp16 copies of q,k,v inputs
__device__ __half g_wh[3 * WN];   // fp16 copies of Wq,Wk,Wv

__device__ __forceinline__ uint32_t smem_u32(const void* p) {
    uint32_t a;
    asm("{ .reg .u64 t; cvta.to.shared.u64 t, %1; cvt.u32.u64 %0, t; }"
        : "=r"(a) : "l"(p));
    return a;
}
__device__ __forceinline__ float ex2f(float x) {
    float r;
    asm("ex2.approx.ftz.f32 %0, %1;" : "=f"(r) : "f"(x));
    return r;
}
__device__ __forceinline__ uint32_t packh2(float lo, float hi) {
    uint32_t r;  // d<15:0> = cvt(lo), d<31:16> = cvt(hi)
    asm("cvt.rn.f16x2.f32 %0, %1, %2;" : "=r"(r) : "f"(hi), "f"(lo));
    return r;
}
__device__ __forceinline__ void cp_async16(uint32_t dst, const void* src) {
    asm volatile("cp.async.cg.shared.global [%0], [%1], 16;"
                 :: "r"(dst), "l"(src) : "memory");
}
__device__ __forceinline__ void mma_f16(float* d, uint32_t a0, uint32_t a1,
                                        uint32_t a2, uint32_t a3,
                                        uint32_t b0, uint32_t b1) {
    asm volatile(
        "mma.sync.aligned.m16n8k16.row.col.f32.f16.f16.f32 "
        "{%0,%1,%2,%3}, {%4,%5,%6,%7}, {%8,%9}, {%0,%1,%2,%3};"
        : "+f"(d[0]), "+f"(d[1]), "+f"(d[2]), "+f"(d[3])
        : "r"(a0), "r"(a1), "r"(a2), "r"(a3), "r"(b0), "r"(b1));
}

// ---------------------------------------------------------------------------
// Pre-pass: convert X (q,k,v) and W (Wq,Wk,Wv) fp32 -> fp16 gmem copies.
// ---------------------------------------------------------------------------
__global__ __launch_bounds__(256)
void cvt16_kernel(const float* __restrict__ q, const float* __restrict__ k,
                  const float* __restrict__ v, const float* __restrict__ Wq,
                  const float* __restrict__ Wk, const float* __restrict__ Wv)
{
    const int z = blockIdx.y;
    const float* src;
    __half* dst;
    size_t i;
    if (blockIdx.x < 8192) {
        src = (z == 0) ? q : (z == 1) ? k : v;
        dst = g_xh + z * XN;
        i = ((size_t)blockIdx.x * 256 + threadIdx.x) * 4;
    } else {
        src = (z == 0) ? Wq : (z == 1) ? Wk : Wv;
        dst = g_wh + z * WN;
        i = ((size_t)(blockIdx.x - 8192) * 256 + threadIdx.x) * 4;
    }
    float4 x = *(const float4*)&src[i];
    __half2 h01 = __floats2half2_rn(x.x, x.y);
    __half2 h23 = __floats2half2_rn(x.z, x.w);
    *(uint2*)&dst[i] = make_uint2(*(uint32_t*)&h01, *(uint32_t*)&h23);
}

// ---------------------------------------------------------------------------
// Projection GEMM, all-fp16 smem + ldmatrix fragments.
// CTA 128x128, BK=64, 3-stage cp.async ring (wait_group 1). 8 warps (2x4).
// ---------------------------------------------------------------------------
#define PAH 72
#define PBH 136
#define AH_ST (128 * PAH)         /* 9216 halves */
#define BH_ST (64 * PBH)          /* 8704 halves */
#define STG_H (AH_ST + BH_ST)     /* 17920 halves per stage */
#define PROJ_SMEM_BYTES (3 * STG_H * 2)   /* 107520 B */
#define PCH 136

__global__ __launch_bounds__(256, 2)
void proj_h_kernel()
{
    extern __shared__ __half hsm[];
    const int z = blockIdx.z;
    const __half* X = g_xh + z * XN;
    const __half* W = g_wh + z * WN;
    __half* O = (z == 0) ? g_qh : (z == 1) ? g_kh : g_vh;

    const int m0 = blockIdx.y * 128;
    const int n0 = blockIdx.x * 128;
    const int tid = threadIdx.x;
    const int lane = tid & 31;
    const int warp = tid >> 5;
    const int wm = (warp >> 2) * 64;
    const int wn = (warp & 3) * 32;
    const int g = lane >> 2, t = lane & 3;

    uint32_t uA[3], uB[3];
#pragma unroll
    for (int i = 0; i < 3; i++) {
        uA[i] = smem_u32(hsm + i * STG_H);
        uB[i] = uA[i] + AH_ST * 2;
    }

    float acc[4][4][4];
#pragma unroll
    for (int i = 0; i < 4; i++)
#pragma unroll
        for (int j = 0; j < 4; j++)
#pragma unroll
            for (int c = 0; c < 4; c++) acc[i][j][c] = 0.f;

    auto issue = [&](int kt) {
        const int st = kt % 3;
        const int k0 = kt * 64;
#pragma unroll
        for (int i = 0; i < 4; i++) {
            int idx = tid + i * 256;
            int row = idx >> 3, c16 = idx & 7;
            cp_async16(uA[st] + (uint32_t)(row * PAH * 2 + c16 * 16),
                       &X[(size_t)(m0 + row) * DM + k0 + c16 * 8]);
        }
#pragma unroll
        for (int i = 0; i < 4; i++) {
            int idx = tid + i * 256;
            int row = idx >> 4, c16 = idx & 15;
            cp_async16(uB[st] + (uint32_t)(row * PBH * 2 + c16 * 16),
                       &W[(size_t)(k0 + row) * DM + n0 + c16 * 8]);
        }
        asm volatile("cp.async.commit_group;" ::: "memory");
    };

    issue(0);
    issue(1);

    const uint32_t a_lane_off =
        (uint32_t)((lane & 15) * PAH * 2 + (lane >> 4) * 16);
    const uint32_t b_lane_off =
        (uint32_t)(((lane & 7) + ((lane >> 3) & 1) * 8) * PBH * 2 +
                   (lane >> 4) * 16);

    const int NSTAGE = DM / 64;   // 16
    for (int kt = 0; kt < NSTAGE; kt++) {
        if (kt + 1 < NSTAGE)
            asm volatile("cp.async.wait_group 1;" ::: "memory");
        else
            asm volatile("cp.async.wait_group 0;" ::: "memory");
        __syncthreads();
        if (kt + 2 < NSTAGE) issue(kt + 2);

        const int st = kt % 3;
        const uint32_t uAs = uA[st];
        const uint32_t uBs = uB[st];
#pragma unroll
        for (int kc = 0; kc < 4; kc++) {
            uint32_t a[4][4];
#pragma unroll
            for (int mf = 0; mf < 4; mf++) {
                uint32_t addr = uAs +
                    (uint32_t)((wm + mf * 16) * PAH + kc * 16) * 2 + a_lane_off;
                asm volatile(
                    "ldmatrix.sync.aligned.m8n8.x4.shared.b16 "
                    "{%0,%1,%2,%3}, [%4];"
                    : "=r"(a[mf][0]), "=r"(a[mf][1]),
                      "=r"(a[mf][2]), "=r"(a[mf][3])
                    : "r"(addr));
            }
            uint32_t brow = uBs + (uint32_t)(kc * 16 * PBH) * 2 + b_lane_off;
#pragma unroll
            for (int dp = 0; dp < 2; dp++) {
                uint32_t b0, b1, b2, b3;
                asm volatile(
                    "ldmatrix.sync.aligned.m8n8.x4.trans.shared.b16 "
                    "{%0,%1,%2,%3}, [%4];"
                    : "=r"(b0), "=r"(b1), "=r"(b2), "=r"(b3)
                    : "r"(brow + (uint32_t)(wn + dp * 16) * 2));
#pragma unroll
                for (int mf = 0; mf < 4; mf++) {
                    mma_f16(acc[mf][dp * 2], a[mf][0], a[mf][1], a[mf][2],
                            a[mf][3], b0, b1);
                    mma_f16(acc[mf][dp * 2 + 1], a[mf][0], a[mf][1], a[mf][2],
                            a[mf][3], b2, b3);
                }
            }
        }
    }

    // ---- Epilogue: fp16 staging tile, coalesced sweep ----
    __syncthreads();
    __half* ct = hsm;   // [128][PCH]
#pragma unroll
    for (int mf = 0; mf < 4; mf++) {
#pragma unroll
        for (int nf = 0; nf < 4; nf++) {
            int ml = wm + mf * 16 + g;
            int nb = wn + nf * 8 + 2 * t;
            __half2 lo = __floats2half2_rn(acc[mf][nf][0], acc[mf][nf][1]);
            __half2 hi = __floats2half2_rn(acc[mf][nf][2], acc[mf][nf][3]);
            *(__half2*)&ct[ml * PCH + nb] = lo;
            *(__half2*)&ct[(ml + 8) * PCH + nb] = hi;
        }
    }
    __syncthreads();

#pragma unroll
    for (int i = 0; i < 8; i++) {
        int idx = tid + i * 256;
        int row = idx >> 4;
        int c16 = idx & 15;
        uint4 val = *(const uint4*)&ct[row * PCH + c16 * 8];
        int m = m0 + row;
        int n = n0 + c16 * 8;
        int b_ = m >> 11, s = m & 2047, h = n >> 6, d = n & 63;
        size_t base = ((((size_t)b_ * Hh + h) * Ss) + s) * Dh + d;
        *(uint4*)&O[base] = val;
    }
}

// ---------------------------------------------------------------------------
// Flash attention: all-fp16 MMA, 4 warps x 32 q-rows, 3-stage K/V pipeline,
// warp-uniform causal-mask hoist.
// ---------------------------------------------------------------------------
#define SPKH 72
#define SPVH 72
#define KV_FL 2304
#define FA_SMEM_FLOATS (6 * KV_FL + 192)   /* 14016 fl = 56.1 KB */

__global__ __launch_bounds__(128, 2)
void fa_mma_kernel(const float* __restrict__ vmask,
                   const float* __restrict__ qmask, float* __restrict__ out)
{
    extern __shared__ float sm[];
    const int qt = (int)gridDim.x - 1 - (int)blockIdx.x;
    const int bh = blockIdx.y;
    const int b_ = bh >> 4, h = bh & 15;
    const int tid = threadIdx.x, lane = tid & 31, wid = tid >> 5;
    const int g = lane >> 2, t = lane & 3;
    const int wr = wid * 32;

    uint32_t uK[3], uV[3], uM[3];
    const float* vmb[3];
#pragma unroll
    for (int i = 0; i < 3; i++) {
        uK[i] = smem_u32(sm + i * KV_FL);
        uV[i] = smem_u32(sm + (3 + i) * KV_FL);
        uM[i] = smem_u32(sm + 6 * KV_FL + i * 64);
        vmb[i] = sm + 6 * KV_FL + i * 64;
    }

    const __half* Kg = &g_kh[(size_t)bh * Ss * Dh];
    const __half* Vg = &g_vh[(size_t)bh * Ss * Dh];

    auto issue = [&](int jt) {
        const int st = jt % 3;
#pragma unroll
        for (int i = 0; i < 4; i++) {
            int idx = tid + i * 128;
            int row = idx >> 3, c16 = idx & 7;
            cp_async16(uK[st] + (uint32_t)(row * SPKH * 2 + c16 * 16),
                       Kg + (size_t)(jt * 64 + row) * Dh + c16 * 8);
        }
#pragma unroll
        for (int i = 0; i < 4; i++) {
            int idx = tid + i * 128;
            int row = idx >> 3, c16 = idx & 7;
            cp_async16(uV[st] + (uint32_t)(row * SPVH * 2 + c16 * 16),
                       Vg + (size_t)(jt * 64 + row) * Dh + c16 * 8);
        }
        if (tid < 16)
            cp_async16(uM[st] + tid * 16,
                       vmask + (size_t)b_ * Ss + jt * 64 + tid * 4);
        asm volatile("cp.async.commit_group;" ::: "memory");
    };

    const int nt = 2 * qt + 2;
    issue(0);
    if (nt > 1) issue(1);

    uint4 q[2][4];
    {
        const __half* Qg = &g_qh[((size_t)bh * Ss + qt * 128) * Dh];
#pragma unroll
        for (int b2 = 0; b2 < 2; b2++)
#pragma unroll
            for (int P = 0; P < 4; P++) {
                int r = wr + 16 * b2 + g;
                uint32_t a0 = *(const uint32_t*)&Qg[(size_t)r * Dh + 16 * P + 2 * t];
                uint32_t a1 = *(const uint32_t*)&Qg[(size_t)(r + 8) * Dh + 16 * P + 2 * t];
                uint32_t a2 = *(const uint32_t*)&Qg[(size_t)r * Dh + 16 * P + 8 + 2 * t];
                uint32_t a3 = *(const uint32_t*)&Qg[(size_t)(r + 8) * Dh + 16 * P + 8 + 2 * t];
                q[b2][P] = make_uint4(a0, a1, a2, a3);
            }
    }

    const float NEG_INF = -__int_as_float(0x7f800000);
    float mi[2][2], li[2][2];
#pragma unroll
    for (int b2 = 0; b2 < 2; b2++) {
        mi[b2][0] = NEG_INF; mi[b2][1] = NEG_INF;
        li[b2][0] = 0.f;     li[b2][1] = 0.f;
    }
    float o[2][8][4];
#pragma unroll
    for (int b2 = 0; b2 < 2; b2++)
#pragma unroll
        for (int i = 0; i < 8; i++)
#pragma unroll
            for (int j = 0; j < 4; j++) o[b2][i][j] = 0.f;

    const uint32_t vtile_off =
        (uint32_t)(((lane & 7) + ((lane >> 3) & 1) * 8) * SPVH * 2 +
                   (lane >> 4) * 16);

    for (int jt = 0; jt < nt; jt++) {
        if (jt + 1 < nt)
            asm volatile("cp.async.wait_group 1;" ::: "memory");
        else
            asm volatile("cp.async.wait_group 0;" ::: "memory");
        __syncthreads();
        if (jt + 2 < nt) issue(jt + 2);

        const int st = jt % 3;
        const __half* ksm = (const __half*)(sm + st * KV_FL);
        const float*  vmp = vmb[st];
        const uint32_t vb = uV[st] + vtile_off;

        float s[2][8][4];
#pragma unroll
        for (int b2 = 0; b2 < 2; b2++)
#pragma unroll
            for (int n = 0; n < 8; n++)
#pragma unroll
                for (int j = 0; j < 4; j++) s[b2][n][j] = 0.f;
#pragma unroll
        for (int P = 0; P < 4; P++) {
#pragma unroll
            for (int n = 0; n < 8; n++) {
                uint32_t b0 = *(const uint32_t*)
                    &ksm[(n * 8 + g) * SPKH + 16 * P + 2 * t];
                uint32_t b1 = *(const uint32_t*)
                    &ksm[(n * 8 + g) * SPKH + 16 * P + 8 + 2 * t];
                mma_f16(s[0][n], q[0][P].x, q[0][P].y, q[0][P].z, q[0][P].w,
                        b0, b1);
                mma_f16(s[1][n], q[1][P].x, q[1][P].y, q[1][P].z, q[1][P].w,
                        b0, b1);
            }
        }

        // scale + key mask (always)
#pragma unroll
        for (int n = 0; n < 8; n++) {
            float va0 = (1.f - vmp[n * 8 + 2 * t]) * BIG2;
            float va1 = (1.f - vmp[n * 8 + 2 * t + 1]) * BIG2;
#pragma unroll
            for (int b2 = 0; b2 < 2; b2++) {
                s[b2][n][0] = s[b2][n][0] * SCALE2 - va0;
                s[b2][n][1] = s[b2][n][1] * SCALE2 - va1;
                s[b2][n][2] = s[b2][n][2] * SCALE2 - va0;
                s[b2][n][3] = s[b2][n][3] * SCALE2 - va1;
            }
        }
        // causal mask (warp-uniform: only diagonal tiles for this warp)
        if (jt * 64 + 63 > qt * 128 + wr) {
#pragma unroll
            for (int n = 0; n < 8; n++) {
                int c0 = jt * 64 + n * 8 + 2 * t;
#pragma unroll
                for (int b2 = 0; b2 < 2; b2++) {
                    const int rb = qt * 128 + wr + 16 * b2 + g;
                    if (c0 > rb) s[b2][n][0] -= BIG2;
                    if (c0 + 1 > rb) s[b2][n][1] -= BIG2;
                    if (c0 > rb + 8) s[b2][n][2] -= BIG2;
                    if (c0 + 1 > rb + 8) s[b2][n][3] -= BIG2;
                }
            }
        }

        // online softmax per block
#pragma unroll
        for (int b2 = 0; b2 < 2; b2++) {
            float rm0 = NEG_INF, rm1 = NEG_INF;
#pragma unroll
            for (int n = 0; n < 8; n++) {
                rm0 = fmaxf(rm0, fmaxf(s[b2][n][0], s[b2][n][1]));
                rm1 = fmaxf(rm1, fmaxf(s[b2][n][2], s[b2][n][3]));
            }
            rm0 = fmaxf(rm0, __shfl_xor_sync(0xffffffffu, rm0, 1));
            rm0 = fmaxf(rm0, __shfl_xor_sync(0xffffffffu, rm0, 2));
            rm1 = fmaxf(rm1, __shfl_xor_sync(0xffffffffu, rm1, 1));
            rm1 = fmaxf(rm1, __shfl_xor_sync(0xffffffffu, rm1, 2));

            float mn0 = fmaxf(mi[b2][0], rm0), mn1 = fmaxf(mi[b2][1], rm1);
            float cr0 = ex2f(mi[b2][0] - mn0), cr1 = ex2f(mi[b2][1] - mn1);
            float rs0 = 0.f, rs1 = 0.f;
#pragma unroll
            for (int n = 0; n < 8; n++) {
                s[b2][n][0] = ex2f(s[b2][n][0] - mn0);
                s[b2][n][1] = ex2f(s[b2][n][1] - mn0);
                s[b2][n][2] = ex2f(s[b2][n][2] - mn1);
                s[b2][n][3] = ex2f(s[b2][n][3] - mn1);
                rs0 += s[b2][n][0] + s[b2][n][1];
                rs1 += s[b2][n][2] + s[b2][n][3];
            }
            rs0 += __shfl_xor_sync(0xffffffffu, rs0, 1);
            rs0 += __shfl_xor_sync(0xffffffffu, rs0, 2);
            rs1 += __shfl_xor_sync(0xffffffffu, rs1, 1);
            rs1 += __shfl_xor_sync(0xffffffffu, rs1, 2);
            li[b2][0] = li[b2][0] * cr0 + rs0;
            li[b2][1] = li[b2][1] * cr1 + rs1;
            mi[b2][0] = mn0; mi[b2][1] = mn1;
#pragma unroll
            for (int nd = 0; nd < 8; nd++) {
                o[b2][nd][0] *= cr0; o[b2][nd][1] *= cr0;
                o[b2][nd][2] *= cr1; o[b2][nd][3] *= cr1;
            }
        }

        // O += P @ V
#pragma unroll
        for (int kb = 0; kb < 4; kb++) {
            uint32_t a0 = packh2(s[0][2 * kb][0], s[0][2 * kb][1]);
            uint32_t a1 = packh2(s[0][2 * kb][2], s[0][2 * kb][3]);
            uint32_t a2 = packh2(s[0][2 * kb + 1][0], s[0][2 * kb + 1][1]);
            uint32_t a3 = packh2(s[0][2 * kb + 1][2], s[0][2 * kb + 1][3]);
            uint32_t c0 = packh2(s[1][2 * kb][0], s[1][2 * kb][1]);
            uint32_t c1 = packh2(s[1][2 * kb][2], s[1][2 * kb][3]);
            uint32_t c2 = packh2(s[1][2 * kb + 1][0], s[1][2 * kb + 1][1]);
            uint32_t c3 = packh2(s[1][2 * kb + 1][2], s[1][2 * kb + 1][3]);
            uint32_t rowoff = (uint32_t)(kb * 16 * SPVH * 2);
#pragma unroll
            for (int dp = 0; dp < 4; dp++) {
                uint32_t b0, b1, b2v, b3;
                asm volatile(
                    "ldmatrix.sync.aligned.m8n8.x4.trans.shared.b16 "
                    "{%0,%1,%2,%3}, [%4];"
                    : "=r"(b0), "=r"(b1), "=r"(b2v), "=r"(b3)
                    : "r"(vb + rowoff + dp * 32));
                mma_f16(o[0][2 * dp], a0, a1, a2, a3, b0, b1);
                mma_f16(o[0][2 * dp + 1], a0, a1, a2, a3, b2v, b3);
                mma_f16(o[1][2 * dp], c0, c1, c2, c3, b0, b1);
                mma_f16(o[1][2 * dp + 1], c0, c1, c2, c3, b2v, b3);
            }
        }
    }

#pragma unroll
    for (int b2 = 0; b2 < 2; b2++) {
        int r0 = qt * 128 + wr + 16 * b2 + g;
        int r1 = r0 + 8;
        float sc0 = qmask[(size_t)b_ * Ss + r0] / li[b2][0];
        float sc1 = qmask[(size_t)b_ * Ss + r1] / li[b2][1];
        float* ob0 = out + ((size_t)b_ * Ss + r0) * DM + h * 64;
        float* ob1 = out + ((size_t)b_ * Ss + r1) * DM + h * 64;
#pragma unroll
        for (int nd = 0; nd < 8; nd++) {
            *(float2*)&ob0[nd * 8 + 2 * t] =
                make_float2(o[b2][nd][0] * sc0, o[b2][nd][1] * sc0);
            *(float2*)&ob1[nd * 8 + 2 * t] =
                make_float2(o[b2][nd][2] * sc1, o[b2][nd][3] * sc1);
        }
    }
}

extern "C" void kernel_launch(void* const* d_in, const int* in_sizes, int n_in,
                              void* d_out, int out_size)
{
    const float* q     = (const float*)d_in[0];
    const float* k     = (const float*)d_in[1];
    const float* v     = (const float*)d_in[2];
    const float* vmask = (const float*)d_in[3];
    const float* qmask = (const float*)d_in[4];
    const float* Wq    = (const float*)d_in[5];
    const float* Wk    = (const float*)d_in[6];
    const float* Wv    = (const float*)d_in[7];
    float* out = (float*)d_out;

    dim3 cg(9216, 3);
    cvt16_kernel<<<cg, 256>>>(q, k, v, Wq, Wk, Wv);

    cudaFuncSetAttribute(proj_h_kernel,
                         cudaFuncAttributeMaxDynamicSharedMemorySize,
                         PROJ_SMEM_BYTES);
    dim3 pg(DM / 128, (Bb * Ss) / 128, 3);
    proj_h_kernel<<<pg, 256, PROJ_SMEM_BYTES>>>();

    int fa_smem = FA_SMEM_FLOATS * sizeof(float);
    cudaFuncSetAttribute(fa_mma_kernel,
                         cudaFuncAttributeMaxDynamicSharedMemorySize, fa_smem);
    dim3 fg(Ss / 128, Bb * Hh);
    fa_mma_kernel<<<fg, 128, fa_smem>>>(vmask, qmask, out);
}

// round 14
// speedup vs baseline: 1.0608x; 1.0608x over previous
#include <cuda_runtime.h>
#include <cuda_fp16.h>
#include <cstdint>

#define Bb 4
#define Ss 2048
#define DM 1024
#define Hh 16
#define Dh 64
// base-2 domain constants
#define SCALE2 0.18033688011112042f   /* 0.125 * log2(e) */
#define BIG2   1.4426950408889634e10f /* 1e10 * log2(e) */

#define XN 8388608ULL   /* Bb*Ss*DM */
#define WN 1048576ULL   /* DM*DM */

// Scratch (allocation-free rule: __device__ globals).
__device__ __half g_qh[Bb * Hh * Ss * Dh];
__device__ __half g_kh[Bb * Hh * Ss * Dh];
__device__ __half g_vh[Bb * Hh * Ss * Dh];
__device__ __half g_xh[3 * XN];   // fp16 copies of q,k,v inputs
__device__ __half g_wh[3 * WN];   // fp16 copies of Wq,Wk,Wv

__device__ __forceinline__ uint32_t smem_u32(const void* p) {
    uint32_t a;
    asm("{ .reg .u64 t; cvta.to.shared.u64 t, %1; cvt.u32.u64 %0, t; }"
        : "=r"(a) : "l"(p));
    return a;
}
__device__ __forceinline__ float ex2f(float x) {
    float r;
    asm("ex2.approx.ftz.f32 %0, %1;" : "=f"(r) : "f"(x));
    return r;
}
__device__ __forceinline__ uint32_t packh2(float lo, float hi) {
    uint32_t r;  // d<15:0> = cvt(lo), d<31:16> = cvt(hi)
    asm("cvt.rn.f16x2.f32 %0, %1, %2;" : "=r"(r) : "f"(hi), "f"(lo));
    return r;
}
__device__ __forceinline__ uint32_t h2exp2(uint32_t x) {
    uint32_t r;  // 2^x elementwise on fp16x2
    asm("ex2.approx.f16x2 %0, %1;" : "=r"(r) : "r"(x));
    return r;
}
__device__ __forceinline__ void cp_async16(uint32_t dst, const void* src) {
    asm volatile("cp.async.cg.shared.global [%0], [%1], 16;"
                 :: "r"(dst), "l"(src) : "memory");
}
__device__ __forceinline__ void mma_f16(float* d, uint32_t a0, uint32_t a1,
                                        uint32_t a2, uint32_t a3,
                                        uint32_t b0, uint32_t b1) {
    asm volatile(
        "mma.sync.aligned.m16n8k16.row.col.f32.f16.f16.f32 "
        "{%0,%1,%2,%3}, {%4,%5,%6,%7}, {%8,%9}, {%0,%1,%2,%3};"
        : "+f"(d[0]), "+f"(d[1]), "+f"(d[2]), "+f"(d[3])
        : "r"(a0), "r"(a1), "r"(a2), "r"(a3), "r"(b0), "r"(b1));
}

// ---------------------------------------------------------------------------
// Pre-pass: convert X (q,k,v) and W (Wq,Wk,Wv) fp32 -> fp16 gmem copies.
// ---------------------------------------------------------------------------
__global__ __launch_bounds__(256)
void cvt16_kernel(const float* __restrict__ q, const float* __restrict__ k,
                  const float* __restrict__ v, const float* __restrict__ Wq,
                  const float* __restrict__ Wk, const float* __restrict__ Wv)
{
    const int z = blockIdx.y;
    const float* src;
    __half* dst;
    size_t i;
    if (blockIdx.x < 8192) {
        src = (z == 0) ? q : (z == 1) ? k : v;
        dst = g_xh + z * XN;
        i = ((size_t)blockIdx.x * 256 + threadIdx.x) * 4;
    } else {
        src = (z == 0) ? Wq : (z == 1) ? Wk : Wv;
        dst = g_wh + z * WN;
        i = ((size_t)(blockIdx.x - 8192) * 256 + threadIdx.x) * 4;
    }
    float4 x = *(const float4*)&src[i];
    __half2 h01 = __floats2half2_rn(x.x, x.y);
    __half2 h23 = __floats2half2_rn(x.z, x.w);
    *(uint2*)&dst[i] = make_uint2(*(uint32_t*)&h01, *(uint32_t*)&h23);
}

// ---------------------------------------------------------------------------
// Projection GEMM (R12 config): all-fp16 smem + ldmatrix fragments.
// CTA 128x128, BK=64, double-buffered cp.async. 8 warps (2x4).
// ---------------------------------------------------------------------------
#define PAH 72
#define PBH 136
#define AH_ST (128 * PAH)
#define BH_ST (64 * PBH)
#define STG_H (AH_ST + BH_ST)
#define PROJ_SMEM_BYTES (2 * STG_H * 2)
#define PCH 136

__global__ __launch_bounds__(256, 2)
void proj_h_kernel()
{
    extern __shared__ __half hsm[];
    const int z = blockIdx.z;
    const __half* X = g_xh + z * XN;
    const __half* W = g_wh + z * WN;
    __half* O = (z == 0) ? g_qh : (z == 1) ? g_kh : g_vh;

    const int m0 = blockIdx.y * 128;
    const int n0 = blockIdx.x * 128;
    const int tid = threadIdx.x;
    const int lane = tid & 31;
    const int warp = tid >> 5;
    const int wm = (warp >> 2) * 64;
    const int wn = (warp & 3) * 32;
    const int g = lane >> 2, t = lane & 3;

    uint32_t uA[2], uB[2];
#pragma unroll
    for (int i = 0; i < 2; i++) {
        uA[i] = smem_u32(hsm + i * STG_H);
        uB[i] = uA[i] + AH_ST * 2;
    }

    float acc[4][4][4];
#pragma unroll
    for (int i = 0; i < 4; i++)
#pragma unroll
        for (int j = 0; j < 4; j++)
#pragma unroll
            for (int c = 0; c < 4; c++) acc[i][j][c] = 0.f;

    auto issue = [&](int kt) {
        const int st = kt & 1;
        const int k0 = kt * 64;
#pragma unroll
        for (int i = 0; i < 4; i++) {
            int idx = tid + i * 256;
            int row = idx >> 3, c16 = idx & 7;
            cp_async16(uA[st] + (uint32_t)(row * PAH * 2 + c16 * 16),
                       &X[(size_t)(m0 + row) * DM + k0 + c16 * 8]);
        }
#pragma unroll
        for (int i = 0; i < 4; i++) {
            int idx = tid + i * 256;
            int row = idx >> 4, c16 = idx & 15;
            cp_async16(uB[st] + (uint32_t)(row * PBH * 2 + c16 * 16),
                       &W[(size_t)(k0 + row) * DM + n0 + c16 * 8]);
        }
        asm volatile("cp.async.commit_group;" ::: "memory");
    };

    issue(0);

    const uint32_t a_lane_off =
        (uint32_t)((lane & 15) * PAH * 2 + (lane >> 4) * 16);
    const uint32_t b_lane_off =
        (uint32_t)(((lane & 7) + ((lane >> 3) & 1) * 8) * PBH * 2 +
                   (lane >> 4) * 16);

    const int NSTAGE = DM / 64;   // 16
    for (int kt = 0; kt < NSTAGE; kt++) {
        asm volatile("cp.async.wait_group 0;" ::: "memory");
        __syncthreads();
        if (kt + 1 < NSTAGE) issue(kt + 1);

        const int st = kt & 1;
        const uint32_t uAs = uA[st];
        const uint32_t uBs = uB[st];
#pragma unroll
        for (int kc = 0; kc < 4; kc++) {
            uint32_t a[4][4];
#pragma unroll
            for (int mf = 0; mf < 4; mf++) {
                uint32_t addr = uAs +
                    (uint32_t)((wm + mf * 16) * PAH + kc * 16) * 2 + a_lane_off;
                asm volatile(
                    "ldmatrix.sync.aligned.m8n8.x4.shared.b16 "
                    "{%0,%1,%2,%3}, [%4];"
                    : "=r"(a[mf][0]), "=r"(a[mf][1]),
                      "=r"(a[mf][2]), "=r"(a[mf][3])
                    : "r"(addr));
            }
            uint32_t brow = uBs + (uint32_t)(kc * 16 * PBH) * 2 + b_lane_off;
#pragma unroll
            for (int dp = 0; dp < 2; dp++) {
                uint32_t b0, b1, b2, b3;
                asm volatile(
                    "ldmatrix.sync.aligned.m8n8.x4.trans.shared.b16 "
                    "{%0,%1,%2,%3}, [%4];"
                    : "=r"(b0), "=r"(b1), "=r"(b2), "=r"(b3)
                    : "r"(brow + (uint32_t)(wn + dp * 16) * 2));
#pragma unroll
                for (int mf = 0; mf < 4; mf++) {
                    mma_f16(acc[mf][dp * 2], a[mf][0], a[mf][1], a[mf][2],
                            a[mf][3], b0, b1);
                    mma_f16(acc[mf][dp * 2 + 1], a[mf][0], a[mf][1], a[mf][2],
                            a[mf][3], b2, b3);
                }
            }
        }
    }

    // ---- Epilogue: fp16 staging tile, coalesced sweep ----
    __syncthreads();
    __half* ct = hsm;   // [128][PCH]
#pragma unroll
    for (int mf = 0; mf < 4; mf++) {
#pragma unroll
        for (int nf = 0; nf < 4; nf++) {
            int ml = wm + mf * 16 + g;
            int nb = wn + nf * 8 + 2 * t;
            __half2 lo = __floats2half2_rn(acc[mf][nf][0], acc[mf][nf][1]);
            __half2 hi = __floats2half2_rn(acc[mf][nf][2], acc[mf][nf][3]);
            *(__half2*)&ct[ml * PCH + nb] = lo;
            *(__half2*)&ct[(ml + 8) * PCH + nb] = hi;
        }
    }
    __syncthreads();

#pragma unroll
    for (int i = 0; i < 8; i++) {
        int idx = tid + i * 256;
        int row = idx >> 4;
        int c16 = idx & 15;
        uint4 val = *(const uint4*)&ct[row * PCH + c16 * 8];
        int m = m0 + row;
        int n = n0 + c16 * 8;
        int b_ = m >> 11, s = m & 2047, h = n >> 6, d = n & 63;
        size_t base = ((((size_t)b_ * Hh + h) * Ss) + s) * Dh + d;
        *(uint4*)&O[base] = val;
    }
}

// ---------------------------------------------------------------------------
// Flash attention: all-fp16 MMA, 4 warps x 32 q-rows, double-buffered.
// Softmax: ex2.approx.f16x2 (inputs packed pre-exp), row sums via ones-MMA.
// Causal mask hoisted on warp-uniform predicate.
// ---------------------------------------------------------------------------
#define SPKH 72
#define SPVH 72
#define KV_FL 2304
#define FA_SMEM_FLOATS (4 * KV_FL + 128)

__global__ __launch_bounds__(128, 2)
void fa_mma_kernel(const float* __restrict__ vmask,
                   const float* __restrict__ qmask, float* __restrict__ out)
{
    extern __shared__ float sm[];
    __half* Kh0  = (__half*)sm;
    __half* Kh1  = (__half*)(sm + KV_FL);
    __half* Vh0  = (__half*)(sm + 2 * KV_FL);
    __half* Vh1  = (__half*)(sm + 3 * KV_FL);
    float*  vm0b = sm + 4 * KV_FL;
    float*  vm1b = vm0b + 64;

    const int qt = (int)gridDim.x - 1 - (int)blockIdx.x;
    const int bh = blockIdx.y;
    const int b_ = bh >> 4, h = bh & 15;
    const int tid = threadIdx.x, lane = tid & 31, wid = tid >> 5;
    const int g = lane >> 2, t = lane & 3;
    const int wr = wid * 32;

    const uint32_t uK[2] = { smem_u32(Kh0), smem_u32(Kh1) };
    const uint32_t uV[2] = { smem_u32(Vh0), smem_u32(Vh1) };
    const uint32_t uM[2] = { smem_u32(vm0b), smem_u32(vm1b) };

    const __half* Kg = &g_kh[(size_t)bh * Ss * Dh];
    const __half* Vg = &g_vh[(size_t)bh * Ss * Dh];

    auto issue = [&](int jt, int bsel) {
#pragma unroll
        for (int i = 0; i < 4; i++) {
            int idx = tid + i * 128;
            int row = idx >> 3, c16 = idx & 7;
            cp_async16(uK[bsel] + (uint32_t)(row * SPKH * 2 + c16 * 16),
                       Kg + (size_t)(jt * 64 + row) * Dh + c16 * 8);
        }
#pragma unroll
        for (int i = 0; i < 4; i++) {
            int idx = tid + i * 128;
            int row = idx >> 3, c16 = idx & 7;
            cp_async16(uV[bsel] + (uint32_t)(row * SPVH * 2 + c16 * 16),
                       Vg + (size_t)(jt * 64 + row) * Dh + c16 * 8);
        }
        if (tid < 16)
            cp_async16(uM[bsel] + tid * 16,
                       vmask + (size_t)b_ * Ss + jt * 64 + tid * 4);
        asm volatile("cp.async.commit_group;" ::: "memory");
    };

    issue(0, 0);

    uint4 q[2][4];
    {
        const __half* Qg = &g_qh[((size_t)bh * Ss + qt * 128) * Dh];
#pragma unroll
        for (int b2 = 0; b2 < 2; b2++)
#pragma unroll
            for (int P = 0; P < 4; P++) {
                int r = wr + 16 * b2 + g;
                uint32_t a0 = *(const uint32_t*)&Qg[(size_t)r * Dh + 16 * P + 2 * t];
                uint32_t a1 = *(const uint32_t*)&Qg[(size_t)(r + 8) * Dh + 16 * P + 2 * t];
                uint32_t a2 = *(const uint32_t*)&Qg[(size_t)r * Dh + 16 * P + 8 + 2 * t];
                uint32_t a3 = *(const uint32_t*)&Qg[(size_t)(r + 8) * Dh + 16 * P + 8 + 2 * t];
                q[b2][P] = make_uint4(a0, a1, a2, a3);
            }
    }

    const float NEG_INF = -__int_as_float(0x7f800000);
    const uint32_t HONES = 0x3C003C00u;   // fp16x2 {1.0, 1.0}
    float mi[2][2];
    float lacc[2][4];                     // l via ones-MMA: [0,1]=r0, [2,3]=r1
#pragma unroll
    for (int b2 = 0; b2 < 2; b2++) {
        mi[b2][0] = NEG_INF; mi[b2][1] = NEG_INF;
#pragma unroll
        for (int j = 0; j < 4; j++) lacc[b2][j] = 0.f;
    }
    float o[2][8][4];
#pragma unroll
    for (int b2 = 0; b2 < 2; b2++)
#pragma unroll
        for (int i = 0; i < 8; i++)
#pragma unroll
            for (int j = 0; j < 4; j++) o[b2][i][j] = 0.f;

    const uint32_t vtile_off =
        (uint32_t)(((lane & 7) + ((lane >> 3) & 1) * 8) * SPVH * 2 +
                   (lane >> 4) * 16);

    const int nt = 2 * qt + 2;
    for (int jt = 0; jt < nt; jt++) {
        const int bsel = jt & 1;
        asm volatile("cp.async.wait_group 0;" ::: "memory");
        __syncthreads();
        if (jt + 1 < nt) issue(jt + 1, bsel ^ 1);

        const __half* ksm = bsel ? Kh1 : Kh0;
        const float*  vmp = bsel ? vm1b : vm0b;
        const uint32_t vb = uV[bsel] + vtile_off;

        float s[2][8][4];
#pragma unroll
        for (int b2 = 0; b2 < 2; b2++)
#pragma unroll
            for (int n = 0; n < 8; n++)
#pragma unroll
                for (int j = 0; j < 4; j++) s[b2][n][j] = 0.f;
#pragma unroll
        for (int P = 0; P < 4; P++) {
#pragma unroll
            for (int n = 0; n < 8; n++) {
                uint32_t b0 = *(const uint32_t*)
                    &ksm[(n * 8 + g) * SPKH + 16 * P + 2 * t];
                uint32_t b1 = *(const uint32_t*)
                    &ksm[(n * 8 + g) * SPKH + 16 * P + 8 + 2 * t];
                mma_f16(s[0][n], q[0][P].x, q[0][P].y, q[0][P].z, q[0][P].w,
                        b0, b1);
                mma_f16(s[1][n], q[1][P].x, q[1][P].y, q[1][P].z, q[1][P].w,
                        b0, b1);
            }
        }

        // scale + key mask (always)
#pragma unroll
        for (int n = 0; n < 8; n++) {
            float va0 = (1.f - vmp[n * 8 + 2 * t]) * BIG2;
            float va1 = (1.f - vmp[n * 8 + 2 * t + 1]) * BIG2;
#pragma unroll
            for (int b2 = 0; b2 < 2; b2++) {
                s[b2][n][0] = s[b2][n][0] * SCALE2 - va0;
                s[b2][n][1] = s[b2][n][1] * SCALE2 - va1;
                s[b2][n][2] = s[b2][n][2] * SCALE2 - va0;
                s[b2][n][3] = s[b2][n][3] * SCALE2 - va1;
            }
        }
        // causal mask (warp-uniform: diagonal tiles only)
        if (jt * 64 + 63 > qt * 128 + wr) {
#pragma unroll
            for (int n = 0; n < 8; n++) {
                int c0 = jt * 64 + n * 8 + 2 * t;
#pragma unroll
                for (int b2 = 0; b2 < 2; b2++) {
                    const int rb = qt * 128 + wr + 16 * b2 + g;
                    if (c0 > rb) s[b2][n][0] -= BIG2;
                    if (c0 + 1 > rb) s[b2][n][1] -= BIG2;
                    if (c0 > rb + 8) s[b2][n][2] -= BIG2;
                    if (c0 + 1 > rb + 8) s[b2][n][3] -= BIG2;
                }
            }
        }

        // row max + rescale (l handled by ones-MMA below)
        float mn[2][2];
#pragma unroll
        for (int b2 = 0; b2 < 2; b2++) {
            float rm0 = NEG_INF, rm1 = NEG_INF;
#pragma unroll
            for (int n = 0; n < 8; n++) {
                rm0 = fmaxf(rm0, fmaxf(s[b2][n][0], s[b2][n][1]));
                rm1 = fmaxf(rm1, fmaxf(s[b2][n][2], s[b2][n][3]));
            }
            rm0 = fmaxf(rm0, __shfl_xor_sync(0xffffffffu, rm0, 1));
            rm0 = fmaxf(rm0, __shfl_xor_sync(0xffffffffu, rm0, 2));
            rm1 = fmaxf(rm1, __shfl_xor_sync(0xffffffffu, rm1, 1));
            rm1 = fmaxf(rm1, __shfl_xor_sync(0xffffffffu, rm1, 2));

            float mn0 = fmaxf(mi[b2][0], rm0), mn1 = fmaxf(mi[b2][1], rm1);
            float cr0 = ex2f(mi[b2][0] - mn0), cr1 = ex2f(mi[b2][1] - mn1);
            mi[b2][0] = mn0; mi[b2][1] = mn1;
            mn[b2][0] = mn0; mn[b2][1] = mn1;
            lacc[b2][0] *= cr0; lacc[b2][1] *= cr0;
            lacc[b2][2] *= cr1; lacc[b2][3] *= cr1;
#pragma unroll
            for (int nd = 0; nd < 8; nd++) {
                o[b2][nd][0] *= cr0; o[b2][nd][1] *= cr0;
                o[b2][nd][2] *= cr1; o[b2][nd][3] *= cr1;
            }
        }

        // P = exp2(s - m) in fp16x2; O += P @ V; l += P @ ones
#pragma unroll
        for (int kb = 0; kb < 4; kb++) {
            uint32_t a0 = h2exp2(packh2(s[0][2 * kb][0] - mn[0][0],
                                        s[0][2 * kb][1] - mn[0][0]));
            uint32_t a1 = h2exp2(packh2(s[0][2 * kb][2] - mn[0][1],
                                        s[0][2 * kb][3] - mn[0][1]));
            uint32_t a2 = h2exp2(packh2(s[0][2 * kb + 1][0] - mn[0][0],
                                        s[0][2 * kb + 1][1] - mn[0][0]));
            uint32_t a3 = h2exp2(packh2(s[0][2 * kb + 1][2] - mn[0][1],
                                        s[0][2 * kb + 1][3] - mn[0][1]));
            uint32_t c0 = h2exp2(packh2(s[1][2 * kb][0] - mn[1][0],
                                        s[1][2 * kb][1] - mn[1][0]));
            uint32_t c1 = h2exp2(packh2(s[1][2 * kb][2] - mn[1][1],
                                        s[1][2 * kb][3] - mn[1][1]));
            uint32_t c2 = h2exp2(packh2(s[1][2 * kb + 1][0] - mn[1][0],
                                        s[1][2 * kb + 1][1] - mn[1][0]));
            uint32_t c3 = h2exp2(packh2(s[1][2 * kb + 1][2] - mn[1][1],
                                        s[1][2 * kb + 1][3] - mn[1][1]));
            mma_f16(lacc[0], a0, a1, a2, a3, HONES, HONES);
            mma_f16(lacc[1], c0, c1, c2, c3, HONES, HONES);
            uint32_t rowoff = (uint32_t)(kb * 16 * SPVH * 2);
#pragma unroll
            for (int dp = 0; dp < 4; dp++) {
                uint32_t b0, b1, b2v, b3;
                asm volatile(
                    "ldmatrix.sync.aligned.m8n8.x4.trans.shared.b16 "
                    "{%0,%1,%2,%3}, [%4];"
                    : "=r"(b0), "=r"(b1), "=r"(b2v), "=r"(b3)
                    : "r"(vb + rowoff + dp * 32));
                mma_f16(o[0][2 * dp], a0, a1, a2, a3, b0, b1);
                mma_f16(o[0][2 * dp + 1], a0, a1, a2, a3, b2v, b3);
                mma_f16(o[1][2 * dp], c0, c1, c2, c3, b0, b1);
                mma_f16(o[1][2 * dp + 1], c0, c1, c2, c3, b2v, b3);
            }
        }
    }

#pragma unroll
    for (int b2 = 0; b2 < 2; b2++) {
        int r0 = qt * 128 + wr + 16 * b2 + g;
        int r1 = r0 + 8;
        float sc0 = qmask[(size_t)b_ * Ss + r0] / lacc[b2][0];
        float sc1 = qmask[(size_t)b_ * Ss + r1] / lacc[b2][2];
        float* ob0 = out + ((size_t)b_ * Ss + r0) * DM + h * 64;
        float* ob1 = out + ((size_t)b_ * Ss + r1) * DM + h * 64;
#pragma unroll
        for (int nd = 0; nd < 8; nd++) {
            *(float2*)&ob0[nd * 8 + 2 * t] =
                make_float2(o[b2][nd][0] * sc0, o[b2][nd][1] * sc0);
            *(float2*)&ob1[nd * 8 + 2 * t] =
                make_float2(o[b2][nd][2] * sc1, o[b2][nd][3] * sc1);
        }
    }
}

extern "C" void kernel_launch(void* const* d_in, const int* in_sizes, int n_in,
                              void* d_out, int out_size)
{
    const float* q     = (const float*)d_in[0];
    const float* k     = (const float*)d_in[1];
    const float* v     = (const float*)d_in[2];
    const float* vmask = (const float*)d_in[3];
    const float* qmask = (const float*)d_in[4];
    const float* Wq    = (const float*)d_in[5];
    const float* Wk    = (const float*)d_in[6];
    const float* Wv    = (const float*)d_in[7];
    float* out = (float*)d_out;

    dim3 cg(9216, 3);
    cvt16_kernel<<<cg, 256>>>(q, k, v, Wq, Wk, Wv);

    cudaFuncSetAttribute(proj_h_kernel,
                         cudaFuncAttributeMaxDynamicSharedMemorySize,
                         PROJ_SMEM_BYTES);
    dim3 pg(DM / 128, (Bb * Ss) / 128, 3);
    proj_h_kernel<<<pg, 256, PROJ_SMEM_BYTES>>>();

    int fa_smem = FA_SMEM_FLOATS * sizeof(float);
    cudaFuncSetAttribute(fa_mma_kernel,
                         cudaFuncAttributeMaxDynamicSharedMemorySize, fa_smem);
    dim3 fg(Ss / 128, Bb * Hh);
    fa_mma_kernel<<<fg, 128, fa_smem>>>(vmask, qmask, out);
}